// round 1
// baseline (speedup 1.0000x reference)
#include <cuda_runtime.h>
#include <math.h>

// Problem constants
#define BATCH 32
#define SEQ   4096
#define DIM   512
#define NH    8
#define HD    64
#define LW    512     // word-level length
#define LS    2048    // sub-level length

// ---------------- scratch (static device globals; no allocation) -------------
__device__ float g_fused1[(size_t)BATCH*LS*DIM];   // pooled char embeddings
__device__ float g_proj  [(size_t)BATCH*LS*DIM];   // reused: sub proj -> word proj -> qkv
__device__ float g_sub   [(size_t)BATCH*LS*DIM];
__device__ float g_fused2[(size_t)BATCH*LW*DIM];
__device__ float g_word  [(size_t)BATCH*LW*DIM];
__device__ float g_ta    [(size_t)BATCH*NH*8*32*64];
__device__ float g_tb    [(size_t)BATCH*NH*4*32*64];
__device__ float g_treek [(size_t)BATCH*NH*32*64];
__device__ float g_treev [(size_t)BATCH*NH*32*64];
__device__ float g_state [(size_t)BATCH*NH*15*32*64];
__device__ float g_attn  [(size_t)BATCH*LW*DIM];
__device__ float g_lnout [(size_t)BATCH*LW*DIM];

// ---------------- block reduction -------------------------------------------
__device__ __forceinline__ float blockReduceSum(float v) {
    __shared__ float sh[33];
    __syncthreads();                       // protect sh reuse across calls
    #pragma unroll
    for (int o = 16; o > 0; o >>= 1) v += __shfl_down_sync(0xffffffffu, v, o);
    int lane = threadIdx.x & 31, wid = threadIdx.x >> 5;
    if (lane == 0) sh[wid] = v;
    __syncthreads();
    if (wid == 0) {
        int nw = blockDim.x >> 5;
        v = (lane < nw) ? sh[lane] : 0.f;
        #pragma unroll
        for (int o = 16; o > 0; o >>= 1) v += __shfl_down_sync(0xffffffffu, v, o);
        if (lane == 0) sh[32] = v;
    }
    __syncthreads();
    return sh[32];
}

// ---------------- K1: embed + LN + mean-pool(2) ------------------------------
// one block per sub-position row; 128 threads x 4 floats
__global__ void embed_pool2_kernel(const int* __restrict__ text,
                                   const float* __restrict__ pe,
                                   const float* __restrict__ id_w,
                                   const float* __restrict__ id_b,
                                   const float* __restrict__ eg,
                                   const float* __restrict__ ebeta,
                                   float* __restrict__ out) {
    int row = blockIdx.x;                   // b*LS + j
    int b = row >> 11, j = row & 2047;
    int d = threadIdx.x * 4;
    float4 w4  = *(const float4*)(id_w + d);
    float4 b4  = *(const float4*)(id_b + d);
    float4 g4  = *(const float4*)(eg + d);
    float4 be4 = *(const float4*)(ebeta + d);
    float acc[4] = {0.f, 0.f, 0.f, 0.f};
    #pragma unroll
    for (int i = 0; i < 2; i++) {
        int s = j * 2 + i;
        float c = (float)text[b * SEQ + s];
        float4 p4 = *(const float4*)(pe + (size_t)s * DIM + d);
        float v[4];
        v[0] = c * w4.x + b4.x + p4.x;
        v[1] = c * w4.y + b4.y + p4.y;
        v[2] = c * w4.z + b4.z + p4.z;
        v[3] = c * w4.w + b4.w + p4.w;
        float sum = v[0] + v[1] + v[2] + v[3];
        float mean = blockReduceSum(sum) * (1.f / DIM);
        float sq = 0.f;
        #pragma unroll
        for (int k = 0; k < 4; k++) { float t = v[k] - mean; sq += t * t; }
        float var = blockReduceSum(sq) * (1.f / DIM);
        float rstd = rsqrtf(var + 1e-5f);
        float gg[4] = {g4.x, g4.y, g4.z, g4.w};
        float bb[4] = {be4.x, be4.y, be4.z, be4.w};
        #pragma unroll
        for (int k = 0; k < 4; k++)
            acc[k] += 0.5f * ((v[k] - mean) * rstd * gg[k] + bb[k]);
    }
    float4 o = make_float4(acc[0], acc[1], acc[2], acc[3]);
    *(float4*)(out + (size_t)row * DIM + d) = o;
}

// ---------------- generic fp32 GEMM: C[M,N] = A[M,K] * W[N,K]^T + bias -------
#define BM 128
#define BN 128
#define BKK 16
__global__ __launch_bounds__(256)
void sgemm_nt(const float* __restrict__ A, const float* __restrict__ W,
              const float* __restrict__ bias, float* __restrict__ C,
              int M, int N, int K) {
    __shared__ float As[BKK][BM];
    __shared__ float Bs[BKK][BN];
    int bm = blockIdx.y * BM;
    int bn = blockIdx.x * BN;
    int tid = threadIdx.x;
    int tx = tid & 15, ty = tid >> 4;
    float acc[8][8];
    #pragma unroll
    for (int i = 0; i < 8; i++)
        #pragma unroll
        for (int j = 0; j < 8; j++) acc[i][j] = 0.f;

    for (int k0 = 0; k0 < K; k0 += BKK) {
        #pragma unroll
        for (int i = 0; i < 2; i++) {
            int idx = tid + i * 256;          // 0..511 float4 slots
            int row = idx >> 2;
            int c4  = (idx & 3) * 4;
            float4 va = *(const float4*)&A[(size_t)(bm + row) * K + k0 + c4];
            As[c4 + 0][row] = va.x; As[c4 + 1][row] = va.y;
            As[c4 + 2][row] = va.z; As[c4 + 3][row] = va.w;
            float4 vb = *(const float4*)&W[(size_t)(bn + row) * K + k0 + c4];
            Bs[c4 + 0][row] = vb.x; Bs[c4 + 1][row] = vb.y;
            Bs[c4 + 2][row] = vb.z; Bs[c4 + 3][row] = vb.w;
        }
        __syncthreads();
        #pragma unroll
        for (int k = 0; k < BKK; k++) {
            float a[8], bfr[8];
            #pragma unroll
            for (int i = 0; i < 4; i++) {
                a[i]     = As[k][ty * 4 + i];
                a[4 + i] = As[k][64 + ty * 4 + i];
                bfr[i]     = Bs[k][tx * 4 + i];
                bfr[4 + i] = Bs[k][64 + tx * 4 + i];
            }
            #pragma unroll
            for (int i = 0; i < 8; i++)
                #pragma unroll
                for (int j = 0; j < 8; j++)
                    acc[i][j] = fmaf(a[i], bfr[j], acc[i][j]);
        }
        __syncthreads();
    }
    #pragma unroll
    for (int ih = 0; ih < 2; ih++) {
        #pragma unroll
        for (int i = 0; i < 4; i++) {
            int r = bm + ih * 64 + ty * 4 + i;
            #pragma unroll
            for (int jh = 0; jh < 2; jh++) {
                int c = bn + jh * 64 + tx * 4;
                float4 v;
                float b0 = bias ? bias[c + 0] : 0.f;
                float b1 = bias ? bias[c + 1] : 0.f;
                float b2 = bias ? bias[c + 2] : 0.f;
                float b3 = bias ? bias[c + 3] : 0.f;
                v.x = acc[ih * 4 + i][jh * 4 + 0] + b0;
                v.y = acc[ih * 4 + i][jh * 4 + 1] + b1;
                v.z = acc[ih * 4 + i][jh * 4 + 2] + b2;
                v.w = acc[ih * 4 + i][jh * 4 + 3] + b3;
                *(float4*)&C[(size_t)r * N + c] = v;
            }
        }
    }
}

// ---------------- epilogue: spike gate + residual + LN -----------------------
__global__ void fuse_epi_kernel(const float* __restrict__ proj,
                                const float* __restrict__ fused,
                                const float* __restrict__ th,
                                const float* __restrict__ ng,
                                const float* __restrict__ nb,
                                float* __restrict__ out) {
    int row = blockIdx.x;
    int d = threadIdx.x * 4;
    float4 p4 = *(const float4*)(proj  + (size_t)row * DIM + d);
    float4 f4 = *(const float4*)(fused + (size_t)row * DIM + d);
    float4 t4 = *(const float4*)(th + d);
    float4 g4 = *(const float4*)(ng + d);
    float4 b4 = *(const float4*)(nb + d);
    float p[4] = {p4.x, p4.y, p4.z, p4.w};
    float f[4] = {f4.x, f4.y, f4.z, f4.w};
    float t[4] = {t4.x, t4.y, t4.z, t4.w};
    float v[4];
    #pragma unroll
    for (int k = 0; k < 4; k++)
        v[k] = (p[k] >= t[k] ? p[k] : 0.f) + f[k];
    float mean = blockReduceSum(v[0] + v[1] + v[2] + v[3]) * (1.f / DIM);
    float sq = 0.f;
    #pragma unroll
    for (int k = 0; k < 4; k++) { float z = v[k] - mean; sq += z * z; }
    float rstd = rsqrtf(blockReduceSum(sq) * (1.f / DIM) + 1e-5f);
    float gg[4] = {g4.x, g4.y, g4.z, g4.w};
    float bb[4] = {b4.x, b4.y, b4.z, b4.w};
    float4 o;
    o.x = (v[0] - mean) * rstd * gg[0] + bb[0];
    o.y = (v[1] - mean) * rstd * gg[1] + bb[1];
    o.z = (v[2] - mean) * rstd * gg[2] + bb[2];
    o.w = (v[3] - mean) * rstd * gg[3] + bb[3];
    *(float4*)(out + (size_t)row * DIM + d) = o;
}

// ---------------- mean-pool(4): sub -> fused2 --------------------------------
__global__ void pool4_kernel(const float* __restrict__ sub, float* __restrict__ out) {
    int row = blockIdx.x;                    // b*LW + j
    int b = row >> 9, j = row & 511;
    int d = threadIdx.x * 4;
    float4 s = make_float4(0.f, 0.f, 0.f, 0.f);
    #pragma unroll
    for (int i = 0; i < 4; i++) {
        const float4 a = *(const float4*)(sub + ((size_t)b * LS + j * 4 + i) * DIM + d);
        s.x += a.x; s.y += a.y; s.z += a.z; s.w += a.w;
    }
    s.x *= 0.25f; s.y *= 0.25f; s.z *= 0.25f; s.w *= 0.25f;
    *(float4*)(out + (size_t)row * DIM + d) = s;
}

// ---------------- tree level (one launch per level per pass) -----------------
// src: qkv buffer (src_is_qkv=1, mk selects k=1/v=2) or previous-level buffer
// outbuf layout: [B*NH, nodes, 32, 64]
__global__ __launch_bounds__(256)
void tree_level_kernel(const float* __restrict__ src, int src_is_qkv, int mk,
                       int lo, int nodes, int kpass,
                       const float* __restrict__ nw, const float* __restrict__ nb,
                       const float* __restrict__ nth, const float* __restrict__ ntau,
                       const float* __restrict__ nvr,
                       float* __restrict__ outbuf, float* __restrict__ state) {
    int blk = blockIdx.x;
    int n = blk % nodes;
    int bh = blk / nodes;                    // b*NH + h
    int b = bh >> 3, h = bh & 7;
    __shared__ float si[32 * 64];
    __shared__ float sw[64][65];
    int tid = threadIdx.x;
    // load input chunk
    for (int i = tid; i < 2048; i += 256) {
        float val;
        if (src_is_qkv) {
            int s = i >> 6, d = i & 63;
            int l = n * 32 + s;
            val = src[((size_t)(b * LW + l)) * (3 * DIM) + mk * DIM + h * HD + d];
        } else {
            size_t base = (size_t)bh * (2 * nodes) * 2048;
            val = 0.5f * (src[base + (size_t)(2 * n) * 2048 + i] +
                          src[base + (size_t)(2 * n + 1) * 2048 + i]);
        }
        si[i] = val;
    }
    int node = lo + n;
    for (int i = tid; i < 4096; i += 256) {
        sw[i >> 6][i & 63] = nw[(size_t)node * 4096 + i];
    }
    __syncthreads();
    int e = tid & 63;
    float bias = nb[node * HD + e];
    float th   = nth[node * HD + e];
    float tau  = ntau[node * HD + e];
    float vr   = nvr[node * HD + e];
    #pragma unroll
    for (int k = 0; k < 8; k++) {
        int s = (tid >> 6) + k * 4;
        float p = bias;
        #pragma unroll
        for (int d = 0; d < 64; d++)
            p = fmaf(si[s * 64 + d], sw[e][d], p);
        size_t sidx = (((size_t)bh * 15 + node) * 32 + s) * 64 + e;
        float v = kpass ? p : fmaf(tau, state[sidx], p);
        float sp = (v >= th) ? 1.f : 0.f;
        if (kpass) state[sidx] = v * (1.f - sp) + vr * sp;
        outbuf[(((size_t)bh * nodes + n) * 32 + s) * 64 + e] = p * sp;
    }
}

// ---------------- attention over 32 tree keys --------------------------------
__global__ __launch_bounds__(256)
void attn_kernel(const float* __restrict__ qkv, const float* __restrict__ tk,
                 const float* __restrict__ tv, float* __restrict__ attn) {
    int bh = blockIdx.x;
    int b = bh >> 3, h = bh & 7;
    __shared__ float sk[32 * 64];
    __shared__ float sv[32 * 64];
    int tid = threadIdx.x;
    for (int i = tid; i < 2048; i += 256) {
        sk[i] = tk[(size_t)bh * 2048 + i];
        sv[i] = tv[(size_t)bh * 2048 + i];
    }
    __syncthreads();
    #pragma unroll 1
    for (int r = 0; r < 2; r++) {
        int l = tid + r * 256;
        const float4* qp = (const float4*)&qkv[((size_t)(b * LW + l)) * (3 * DIM) + h * HD];
        float q[64];
        #pragma unroll
        for (int i = 0; i < 16; i++) {
            float4 t = qp[i];
            q[i * 4 + 0] = t.x; q[i * 4 + 1] = t.y; q[i * 4 + 2] = t.z; q[i * 4 + 3] = t.w;
        }
        float sc[32];
        float mx = -1e30f;
        #pragma unroll
        for (int j = 0; j < 32; j++) {
            float s = 0.f;
            #pragma unroll
            for (int d = 0; d < 64; d++) s = fmaf(q[d], sk[j * 64 + d], s);
            s *= 0.125f;
            sc[j] = s;
            mx = fmaxf(mx, s);
        }
        float den = 0.f;
        #pragma unroll
        for (int j = 0; j < 32; j++) { sc[j] = expf(sc[j] - mx); den += sc[j]; }
        float inv = 1.f / den;
        float o[64];
        #pragma unroll
        for (int d = 0; d < 64; d++) o[d] = 0.f;
        #pragma unroll
        for (int j = 0; j < 32; j++) {
            float pj = sc[j];
            #pragma unroll
            for (int d = 0; d < 64; d++) o[d] = fmaf(pj, sv[j * 64 + d], o[d]);
        }
        float4* op = (float4*)&attn[((size_t)(b * LW + l)) * DIM + h * HD];
        #pragma unroll
        for (int i = 0; i < 16; i++) {
            float4 t;
            t.x = o[i * 4 + 0] * inv; t.y = o[i * 4 + 1] * inv;
            t.z = o[i * 4 + 2] * inv; t.w = o[i * 4 + 3] * inv;
            op[i] = t;
        }
    }
}

// ---------------- output LN (attn + word residual) ---------------------------
__global__ void out_ln_kernel(const float* __restrict__ attn, const float* __restrict__ word,
                              const float* __restrict__ ng, const float* __restrict__ nb,
                              float* __restrict__ out) {
    int row = blockIdx.x;
    int d = threadIdx.x * 4;
    float4 a4 = *(const float4*)(attn + (size_t)row * DIM + d);
    float4 w4 = *(const float4*)(word + (size_t)row * DIM + d);
    float4 g4 = *(const float4*)(ng + d);
    float4 b4 = *(const float4*)(nb + d);
    float v[4] = {a4.x + w4.x, a4.y + w4.y, a4.z + w4.z, a4.w + w4.w};
    float mean = blockReduceSum(v[0] + v[1] + v[2] + v[3]) * (1.f / DIM);
    float sq = 0.f;
    #pragma unroll
    for (int k = 0; k < 4; k++) { float z = v[k] - mean; sq += z * z; }
    float rstd = rsqrtf(blockReduceSum(sq) * (1.f / DIM) + 1e-5f);
    float gg[4] = {g4.x, g4.y, g4.z, g4.w};
    float bb[4] = {b4.x, b4.y, b4.z, b4.w};
    float4 o;
    o.x = (v[0] - mean) * rstd * gg[0] + bb[0];
    o.y = (v[1] - mean) * rstd * gg[1] + bb[1];
    o.z = (v[2] - mean) * rstd * gg[2] + bb[2];
    o.w = (v[3] - mean) * rstd * gg[3] + bb[3];
    *(float4*)(out + (size_t)row * DIM + d) = o;
}

// ---------------- linear interpolation L=512 -> S=4096 -----------------------
__global__ void interp_kernel(const float* __restrict__ lnout, float* __restrict__ out) {
    int row = blockIdx.x;                    // b*SEQ + s
    int b = row >> 12, s = row & 4095;
    float src = fmaxf((s + 0.5f) * 0.125f - 0.5f, 0.f);
    int i0 = (int)src;
    int i1 = min(i0 + 1, LW - 1);
    float w1 = src - (float)i0;
    float w0 = 1.f - w1;
    int d = threadIdx.x * 4;
    float4 a = *(const float4*)(lnout + ((size_t)b * LW + i0) * DIM + d);
    float4 c = *(const float4*)(lnout + ((size_t)b * LW + i1) * DIM + d);
    float4 o;
    o.x = a.x * w0 + c.x * w1;
    o.y = a.y * w0 + c.y * w1;
    o.z = a.z * w0 + c.z * w1;
    o.w = a.w * w0 + c.w * w1;
    *(float4*)(out + (size_t)row * DIM + d) = o;
}

// ---------------- launch -----------------------------------------------------
extern "C" void kernel_launch(void* const* d_in, const int* in_sizes, int n_in,
                              void* d_out, int out_size) {
    const int*   text    = (const int*)  d_in[0];
    const float* pe      = (const float*)d_in[1];
    const float* id_w    = (const float*)d_in[2];
    const float* id_b    = (const float*)d_in[3];
    const float* eg      = (const float*)d_in[4];
    const float* ebeta   = (const float*)d_in[5];
    const float* sub_w   = (const float*)d_in[6];
    const float* sub_b   = (const float*)d_in[7];
    const float* sub_th  = (const float*)d_in[8];
    const float* sub_ng  = (const float*)d_in[11];
    const float* sub_nb  = (const float*)d_in[12];
    const float* word_w  = (const float*)d_in[13];
    const float* word_b  = (const float*)d_in[14];
    const float* word_th = (const float*)d_in[15];
    const float* word_ng = (const float*)d_in[18];
    const float* word_nb = (const float*)d_in[19];
    const float* qkv_w   = (const float*)d_in[20];
    const float* qkv_b   = (const float*)d_in[21];
    const float* node_w  = (const float*)d_in[22];
    const float* node_b  = (const float*)d_in[23];
    const float* node_th = (const float*)d_in[24];
    const float* node_tau= (const float*)d_in[25];
    const float* node_vr = (const float*)d_in[26];
    const float* out_ng  = (const float*)d_in[27];
    const float* out_nb  = (const float*)d_in[28];

    float *fused1, *proj, *sub, *fused2, *word, *ta, *tb, *tk, *tv, *state, *attn, *lnout;
    cudaGetSymbolAddress((void**)&fused1, g_fused1);
    cudaGetSymbolAddress((void**)&proj,   g_proj);
    cudaGetSymbolAddress((void**)&sub,    g_sub);
    cudaGetSymbolAddress((void**)&fused2, g_fused2);
    cudaGetSymbolAddress((void**)&word,   g_word);
    cudaGetSymbolAddress((void**)&ta,     g_ta);
    cudaGetSymbolAddress((void**)&tb,     g_tb);
    cudaGetSymbolAddress((void**)&tk,     g_treek);
    cudaGetSymbolAddress((void**)&tv,     g_treev);
    cudaGetSymbolAddress((void**)&state,  g_state);
    cudaGetSymbolAddress((void**)&attn,   g_attn);
    cudaGetSymbolAddress((void**)&lnout,  g_lnout);

    // 1. char embed + LN + pool2
    embed_pool2_kernel<<<BATCH * LS, 128>>>(text, pe, id_w, id_b, eg, ebeta, fused1);

    // 2. sub: GEMM + spike/residual/LN epilogue
    {
        dim3 grid(DIM / BN, (BATCH * LS) / BM);
        sgemm_nt<<<grid, 256>>>(fused1, sub_w, sub_b, proj, BATCH * LS, DIM, DIM);
    }
    fuse_epi_kernel<<<BATCH * LS, 128>>>(proj, fused1, sub_th, sub_ng, sub_nb, sub);

    // 3. word: pool4 + GEMM + epilogue
    pool4_kernel<<<BATCH * LW, 128>>>(sub, fused2);
    {
        dim3 grid(DIM / BN, (BATCH * LW) / BM);
        sgemm_nt<<<grid, 256>>>(fused2, word_w, word_b, proj, BATCH * LW, DIM, DIM);
    }
    fuse_epi_kernel<<<BATCH * LW, 128>>>(proj, fused2, word_th, word_ng, word_nb, word);

    // 4. qkv GEMM (bias folded in); result lives in g_proj
    {
        dim3 grid((3 * DIM) / BN, (BATCH * LW) / BM);
        sgemm_nt<<<grid, 256>>>(word, qkv_w, qkv_b, proj, BATCH * LW, 3 * DIM, DIM);
    }

    // 5. tree: K pass (writes LIF state)
    tree_level_kernel<<<BATCH * NH * 8, 256>>>(proj, 1, 1, 7, 8, 1,
        node_w, node_b, node_th, node_tau, node_vr, ta, state);
    tree_level_kernel<<<BATCH * NH * 4, 256>>>(ta, 0, 0, 3, 4, 1,
        node_w, node_b, node_th, node_tau, node_vr, tb, state);
    tree_level_kernel<<<BATCH * NH * 2, 256>>>(tb, 0, 0, 1, 2, 1,
        node_w, node_b, node_th, node_tau, node_vr, ta, state);
    tree_level_kernel<<<BATCH * NH * 1, 256>>>(ta, 0, 0, 0, 1, 1,
        node_w, node_b, node_th, node_tau, node_vr, tk, state);

    // 6. tree: V pass (reads K-pass state; no state write)
    tree_level_kernel<<<BATCH * NH * 8, 256>>>(proj, 1, 2, 7, 8, 0,
        node_w, node_b, node_th, node_tau, node_vr, ta, state);
    tree_level_kernel<<<BATCH * NH * 4, 256>>>(ta, 0, 0, 3, 4, 0,
        node_w, node_b, node_th, node_tau, node_vr, tb, state);
    tree_level_kernel<<<BATCH * NH * 2, 256>>>(tb, 0, 0, 1, 2, 0,
        node_w, node_b, node_th, node_tau, node_vr, ta, state);
    tree_level_kernel<<<BATCH * NH * 1, 256>>>(ta, 0, 0, 0, 1, 0,
        node_w, node_b, node_th, node_tau, node_vr, tv, state);

    // 7. attention + output LN + interpolation
    attn_kernel<<<BATCH * NH, 256>>>(proj, tk, tv, attn);
    out_ln_kernel<<<BATCH * LW, 128>>>(attn, word, out_ng, out_nb, lnout);
    interp_kernel<<<BATCH * SEQ, 128>>>(lnout, (float*)d_out);
}

// round 2
// speedup vs baseline: 1.0546x; 1.0546x over previous
#include <cuda_runtime.h>
#include <math.h>

// Problem constants
#define BATCH 32
#define SEQ   4096
#define DIM   512
#define NH    8
#define HD    64
#define LW    512     // word-level length
#define LS    2048    // sub-level length

typedef unsigned long long ull;

// ---------------- scratch (static device globals; no allocation) -------------
__device__ float g_fused1[(size_t)BATCH*LS*DIM];   // pooled char embeddings
__device__ float g_proj  [(size_t)BATCH*LS*DIM];   // reused: sub proj -> word proj -> qkv
__device__ float g_fused2[(size_t)BATCH*LW*DIM];
__device__ float g_word  [(size_t)BATCH*LW*DIM];
__device__ float g_ta    [(size_t)BATCH*NH*8*32*64];
__device__ float g_tb    [(size_t)BATCH*NH*4*32*64];
__device__ float g_treek [(size_t)BATCH*NH*32*64];
__device__ float g_treev [(size_t)BATCH*NH*32*64];
__device__ float g_state [(size_t)BATCH*NH*15*32*64];
__device__ float g_attn  [(size_t)BATCH*LW*DIM];
__device__ float g_lnout [(size_t)BATCH*LW*DIM];

// ---------------- f32x2 helpers ----------------------------------------------
__device__ __forceinline__ ull pack_dup(float a) {
    ull r; asm("mov.b64 %0, {%1, %1};" : "=l"(r) : "f"(a)); return r;
}
__device__ __forceinline__ void fma2(ull& d, ull a, ull b) {
    asm("fma.rn.f32x2 %0, %1, %2, %3;" : "=l"(d) : "l"(a), "l"(b), "l"(d));
}
__device__ __forceinline__ void unpack2(ull v, float& lo, float& hi) {
    asm("mov.b64 {%0, %1}, %2;" : "=f"(lo), "=f"(hi) : "l"(v));
}

// ---------------- block reduction -------------------------------------------
__device__ __forceinline__ float blockReduceSum(float v) {
    __shared__ float sh[33];
    __syncthreads();                       // protect sh reuse across calls
    #pragma unroll
    for (int o = 16; o > 0; o >>= 1) v += __shfl_down_sync(0xffffffffu, v, o);
    int lane = threadIdx.x & 31, wid = threadIdx.x >> 5;
    if (lane == 0) sh[wid] = v;
    __syncthreads();
    if (wid == 0) {
        int nw = blockDim.x >> 5;
        v = (lane < nw) ? sh[lane] : 0.f;
        #pragma unroll
        for (int o = 16; o > 0; o >>= 1) v += __shfl_down_sync(0xffffffffu, v, o);
        if (lane == 0) sh[32] = v;
    }
    __syncthreads();
    return sh[32];
}

// ---------------- K1: embed + LN + mean-pool(2) ------------------------------
__global__ void embed_pool2_kernel(const int* __restrict__ text,
                                   const float* __restrict__ pe,
                                   const float* __restrict__ id_w,
                                   const float* __restrict__ id_b,
                                   const float* __restrict__ eg,
                                   const float* __restrict__ ebeta,
                                   float* __restrict__ out) {
    int row = blockIdx.x;                   // b*LS + j
    int b = row >> 11, j = row & 2047;
    int d = threadIdx.x * 4;
    float4 w4  = *(const float4*)(id_w + d);
    float4 b4  = *(const float4*)(id_b + d);
    float4 g4  = *(const float4*)(eg + d);
    float4 be4 = *(const float4*)(ebeta + d);
    float acc[4] = {0.f, 0.f, 0.f, 0.f};
    #pragma unroll
    for (int i = 0; i < 2; i++) {
        int s = j * 2 + i;
        float c = (float)text[b * SEQ + s];
        float4 p4 = *(const float4*)(pe + (size_t)s * DIM + d);
        float v[4];
        v[0] = c * w4.x + b4.x + p4.x;
        v[1] = c * w4.y + b4.y + p4.y;
        v[2] = c * w4.z + b4.z + p4.z;
        v[3] = c * w4.w + b4.w + p4.w;
        float sum = v[0] + v[1] + v[2] + v[3];
        float mean = blockReduceSum(sum) * (1.f / DIM);
        float sq = 0.f;
        #pragma unroll
        for (int k = 0; k < 4; k++) { float t = v[k] - mean; sq += t * t; }
        float var = blockReduceSum(sq) * (1.f / DIM);
        float rstd = rsqrtf(var + 1e-5f);
        float gg[4] = {g4.x, g4.y, g4.z, g4.w};
        float bb[4] = {be4.x, be4.y, be4.z, be4.w};
        #pragma unroll
        for (int k = 0; k < 4; k++)
            acc[k] += 0.5f * ((v[k] - mean) * rstd * gg[k] + bb[k]);
    }
    float4 o = make_float4(acc[0], acc[1], acc[2], acc[3]);
    *(float4*)(out + (size_t)row * DIM + d) = o;
}

// ---------------- fp32 GEMM with packed f32x2 FMA ----------------------------
// C[M,N] = A[M,K] * W[N,K]^T + bias
#define BM 128
#define BN 128
#define BKK 16
__global__ __launch_bounds__(256)
void sgemm_nt(const float* __restrict__ A, const float* __restrict__ W,
              const float* __restrict__ bias, float* __restrict__ C,
              int M, int N, int K) {
    __shared__ __align__(16) float As[BKK][BM];
    __shared__ __align__(16) float Bs[BKK][BN];
    int bm = blockIdx.y * BM;
    int bn = blockIdx.x * BN;
    int tid = threadIdx.x;
    int tx = tid & 15, ty = tid >> 4;
    // accumulators: 8 rows x 4 f32x2 pairs (= 8 cols)
    ull acc[8][4];
    #pragma unroll
    for (int i = 0; i < 8; i++)
        #pragma unroll
        for (int j = 0; j < 4; j++) acc[i][j] = 0ull;

    for (int k0 = 0; k0 < K; k0 += BKK) {
        #pragma unroll
        for (int i = 0; i < 2; i++) {
            int idx = tid + i * 256;          // 0..511 float4 slots
            int row = idx >> 2;
            int c4  = (idx & 3) * 4;
            float4 va = *(const float4*)&A[(size_t)(bm + row) * K + k0 + c4];
            As[c4 + 0][row] = va.x; As[c4 + 1][row] = va.y;
            As[c4 + 2][row] = va.z; As[c4 + 3][row] = va.w;
            float4 vb = *(const float4*)&W[(size_t)(bn + row) * K + k0 + c4];
            Bs[c4 + 0][row] = vb.x; Bs[c4 + 1][row] = vb.y;
            Bs[c4 + 2][row] = vb.z; Bs[c4 + 3][row] = vb.w;
        }
        __syncthreads();
        #pragma unroll
        for (int k = 0; k < BKK; k++) {
            float4 a0 = *(const float4*)&As[k][ty * 4];
            float4 a1 = *(const float4*)&As[k][64 + ty * 4];
            ulonglong2 b0 = *(const ulonglong2*)&Bs[k][tx * 4];
            ulonglong2 b1 = *(const ulonglong2*)&Bs[k][64 + tx * 4];
            ull av[8];
            av[0] = pack_dup(a0.x); av[1] = pack_dup(a0.y);
            av[2] = pack_dup(a0.z); av[3] = pack_dup(a0.w);
            av[4] = pack_dup(a1.x); av[5] = pack_dup(a1.y);
            av[6] = pack_dup(a1.z); av[7] = pack_dup(a1.w);
            ull bv[4] = {b0.x, b0.y, b1.x, b1.y};
            #pragma unroll
            for (int i = 0; i < 8; i++)
                #pragma unroll
                for (int j = 0; j < 4; j++)
                    fma2(acc[i][j], av[i], bv[j]);
        }
        __syncthreads();
    }
    // epilogue: unpack pairs, add bias, store
    #pragma unroll
    for (int ih = 0; ih < 2; ih++) {
        #pragma unroll
        for (int i = 0; i < 4; i++) {
            int r = bm + ih * 64 + ty * 4 + i;
            #pragma unroll
            for (int jh = 0; jh < 2; jh++) {
                int c = bn + jh * 64 + tx * 4;
                float v0, v1, v2, v3;
                unpack2(acc[ih * 4 + i][jh * 2 + 0], v0, v1);
                unpack2(acc[ih * 4 + i][jh * 2 + 1], v2, v3);
                float4 v;
                v.x = v0 + (bias ? bias[c + 0] : 0.f);
                v.y = v1 + (bias ? bias[c + 1] : 0.f);
                v.z = v2 + (bias ? bias[c + 2] : 0.f);
                v.w = v3 + (bias ? bias[c + 3] : 0.f);
                *(float4*)&C[(size_t)r * N + c] = v;
            }
        }
    }
}

// ---------------- sub epilogue: spike+residual+LN fused with mean-pool(4) ----
// one block per word row; processes 4 sub rows, writes only the pooled result
__global__ void fuse_epi_pool4_kernel(const float* __restrict__ proj,
                                      const float* __restrict__ fused,
                                      const float* __restrict__ th,
                                      const float* __restrict__ ng,
                                      const float* __restrict__ nb,
                                      float* __restrict__ out) {
    int wrow = blockIdx.x;                  // b*LW + j  -> sub rows wrow*4 .. +3
    int d = threadIdx.x * 4;
    float4 t4 = *(const float4*)(th + d);
    float4 g4 = *(const float4*)(ng + d);
    float4 b4 = *(const float4*)(nb + d);
    float t[4] = {t4.x, t4.y, t4.z, t4.w};
    float gg[4] = {g4.x, g4.y, g4.z, g4.w};
    float bb[4] = {b4.x, b4.y, b4.z, b4.w};
    float acc[4] = {0.f, 0.f, 0.f, 0.f};
    #pragma unroll
    for (int r = 0; r < 4; r++) {
        size_t row = (size_t)wrow * 4 + r;
        float4 p4 = *(const float4*)(proj  + row * DIM + d);
        float4 f4 = *(const float4*)(fused + row * DIM + d);
        float p[4] = {p4.x, p4.y, p4.z, p4.w};
        float f[4] = {f4.x, f4.y, f4.z, f4.w};
        float v[4];
        #pragma unroll
        for (int k = 0; k < 4; k++)
            v[k] = (p[k] >= t[k] ? p[k] : 0.f) + f[k];
        float mean = blockReduceSum(v[0] + v[1] + v[2] + v[3]) * (1.f / DIM);
        float sq = 0.f;
        #pragma unroll
        for (int k = 0; k < 4; k++) { float z = v[k] - mean; sq += z * z; }
        float rstd = rsqrtf(blockReduceSum(sq) * (1.f / DIM) + 1e-5f);
        #pragma unroll
        for (int k = 0; k < 4; k++)
            acc[k] += 0.25f * ((v[k] - mean) * rstd * gg[k] + bb[k]);
    }
    float4 o = make_float4(acc[0], acc[1], acc[2], acc[3]);
    *(float4*)(out + (size_t)wrow * DIM + d) = o;
}

// ---------------- epilogue: spike gate + residual + LN (word stage) ----------
__global__ void fuse_epi_kernel(const float* __restrict__ proj,
                                const float* __restrict__ fused,
                                const float* __restrict__ th,
                                const float* __restrict__ ng,
                                const float* __restrict__ nb,
                                float* __restrict__ out) {
    int row = blockIdx.x;
    int d = threadIdx.x * 4;
    float4 p4 = *(const float4*)(proj  + (size_t)row * DIM + d);
    float4 f4 = *(const float4*)(fused + (size_t)row * DIM + d);
    float4 t4 = *(const float4*)(th + d);
    float4 g4 = *(const float4*)(ng + d);
    float4 b4 = *(const float4*)(nb + d);
    float p[4] = {p4.x, p4.y, p4.z, p4.w};
    float f[4] = {f4.x, f4.y, f4.z, f4.w};
    float t[4] = {t4.x, t4.y, t4.z, t4.w};
    float v[4];
    #pragma unroll
    for (int k = 0; k < 4; k++)
        v[k] = (p[k] >= t[k] ? p[k] : 0.f) + f[k];
    float mean = blockReduceSum(v[0] + v[1] + v[2] + v[3]) * (1.f / DIM);
    float sq = 0.f;
    #pragma unroll
    for (int k = 0; k < 4; k++) { float z = v[k] - mean; sq += z * z; }
    float rstd = rsqrtf(blockReduceSum(sq) * (1.f / DIM) + 1e-5f);
    float gg[4] = {g4.x, g4.y, g4.z, g4.w};
    float bb[4] = {b4.x, b4.y, b4.z, b4.w};
    float4 o;
    o.x = (v[0] - mean) * rstd * gg[0] + bb[0];
    o.y = (v[1] - mean) * rstd * gg[1] + bb[1];
    o.z = (v[2] - mean) * rstd * gg[2] + bb[2];
    o.w = (v[3] - mean) * rstd * gg[3] + bb[3];
    *(float4*)(out + (size_t)row * DIM + d) = o;
}

// ---------------- tree level (one launch per level per pass) -----------------
__global__ __launch_bounds__(256)
void tree_level_kernel(const float* __restrict__ src, int src_is_qkv, int mk,
                       int lo, int nodes, int kpass,
                       const float* __restrict__ nw, const float* __restrict__ nb,
                       const float* __restrict__ nth, const float* __restrict__ ntau,
                       const float* __restrict__ nvr,
                       float* __restrict__ outbuf, float* __restrict__ state) {
    int blk = blockIdx.x;
    int n = blk % nodes;
    int bh = blk / nodes;                    // b*NH + h
    int b = bh >> 3, h = bh & 7;
    __shared__ float si[32 * 64];
    __shared__ float sw[64][65];
    int tid = threadIdx.x;
    for (int i = tid; i < 2048; i += 256) {
        float val;
        if (src_is_qkv) {
            int s = i >> 6, d = i & 63;
            int l = n * 32 + s;
            val = src[((size_t)(b * LW + l)) * (3 * DIM) + mk * DIM + h * HD + d];
        } else {
            size_t base = (size_t)bh * (2 * nodes) * 2048;
            val = 0.5f * (src[base + (size_t)(2 * n) * 2048 + i] +
                          src[base + (size_t)(2 * n + 1) * 2048 + i]);
        }
        si[i] = val;
    }
    int node = lo + n;
    for (int i = tid; i < 4096; i += 256) {
        sw[i >> 6][i & 63] = nw[(size_t)node * 4096 + i];
    }
    __syncthreads();
    int e = tid & 63;
    float bias = nb[node * HD + e];
    float th   = nth[node * HD + e];
    float tau  = ntau[node * HD + e];
    float vr   = nvr[node * HD + e];
    #pragma unroll
    for (int k = 0; k < 8; k++) {
        int s = (tid >> 6) + k * 4;
        float p = bias;
        #pragma unroll
        for (int d = 0; d < 64; d++)
            p = fmaf(si[s * 64 + d], sw[e][d], p);
        size_t sidx = (((size_t)bh * 15 + node) * 32 + s) * 64 + e;
        float v = kpass ? p : fmaf(tau, state[sidx], p);
        float sp = (v >= th) ? 1.f : 0.f;
        if (kpass) state[sidx] = v * (1.f - sp) + vr * sp;
        outbuf[(((size_t)bh * nodes + n) * 32 + s) * 64 + e] = p * sp;
    }
}

// ---------------- attention over 32 tree keys --------------------------------
__global__ __launch_bounds__(256)
void attn_kernel(const float* __restrict__ qkv, const float* __restrict__ tk,
                 const float* __restrict__ tv, float* __restrict__ attn) {
    int bh = blockIdx.x;
    int b = bh >> 3, h = bh & 7;
    __shared__ float sk[32 * 64];
    __shared__ float sv[32 * 64];
    int tid = threadIdx.x;
    for (int i = tid; i < 2048; i += 256) {
        sk[i] = tk[(size_t)bh * 2048 + i];
        sv[i] = tv[(size_t)bh * 2048 + i];
    }
    __syncthreads();
    #pragma unroll 1
    for (int r = 0; r < 2; r++) {
        int l = tid + r * 256;
        const float4* qp = (const float4*)&qkv[((size_t)(b * LW + l)) * (3 * DIM) + h * HD];
        float q[64];
        #pragma unroll
        for (int i = 0; i < 16; i++) {
            float4 t = qp[i];
            q[i * 4 + 0] = t.x; q[i * 4 + 1] = t.y; q[i * 4 + 2] = t.z; q[i * 4 + 3] = t.w;
        }
        float sc[32];
        float mx = -1e30f;
        #pragma unroll
        for (int j = 0; j < 32; j++) {
            float s = 0.f;
            #pragma unroll
            for (int d = 0; d < 64; d++) s = fmaf(q[d], sk[j * 64 + d], s);
            s *= 0.125f;
            sc[j] = s;
            mx = fmaxf(mx, s);
        }
        float den = 0.f;
        #pragma unroll
        for (int j = 0; j < 32; j++) { sc[j] = expf(sc[j] - mx); den += sc[j]; }
        float inv = 1.f / den;
        float o[64];
        #pragma unroll
        for (int d = 0; d < 64; d++) o[d] = 0.f;
        #pragma unroll
        for (int j = 0; j < 32; j++) {
            float pj = sc[j];
            #pragma unroll
            for (int d = 0; d < 64; d++) o[d] = fmaf(pj, sv[j * 64 + d], o[d]);
        }
        float4* op = (float4*)&attn[((size_t)(b * LW + l)) * DIM + h * HD];
        #pragma unroll
        for (int i = 0; i < 16; i++) {
            float4 t;
            t.x = o[i * 4 + 0] * inv; t.y = o[i * 4 + 1] * inv;
            t.z = o[i * 4 + 2] * inv; t.w = o[i * 4 + 3] * inv;
            op[i] = t;
        }
    }
}

// ---------------- output LN (attn + word residual) ---------------------------
__global__ void out_ln_kernel(const float* __restrict__ attn, const float* __restrict__ word,
                              const float* __restrict__ ng, const float* __restrict__ nb,
                              float* __restrict__ out) {
    int row = blockIdx.x;
    int d = threadIdx.x * 4;
    float4 a4 = *(const float4*)(attn + (size_t)row * DIM + d);
    float4 w4 = *(const float4*)(word + (size_t)row * DIM + d);
    float4 g4 = *(const float4*)(ng + d);
    float4 b4 = *(const float4*)(nb + d);
    float v[4] = {a4.x + w4.x, a4.y + w4.y, a4.z + w4.z, a4.w + w4.w};
    float mean = blockReduceSum(v[0] + v[1] + v[2] + v[3]) * (1.f / DIM);
    float sq = 0.f;
    #pragma unroll
    for (int k = 0; k < 4; k++) { float z = v[k] - mean; sq += z * z; }
    float rstd = rsqrtf(blockReduceSum(sq) * (1.f / DIM) + 1e-5f);
    float gg[4] = {g4.x, g4.y, g4.z, g4.w};
    float bb[4] = {b4.x, b4.y, b4.z, b4.w};
    float4 o;
    o.x = (v[0] - mean) * rstd * gg[0] + bb[0];
    o.y = (v[1] - mean) * rstd * gg[1] + bb[1];
    o.z = (v[2] - mean) * rstd * gg[2] + bb[2];
    o.w = (v[3] - mean) * rstd * gg[3] + bb[3];
    *(float4*)(out + (size_t)row * DIM + d) = o;
}

// ---------------- linear interpolation L=512 -> S=4096 -----------------------
__global__ void interp_kernel(const float* __restrict__ lnout, float* __restrict__ out) {
    int row = blockIdx.x;                    // b*SEQ + s
    int b = row >> 12, s = row & 4095;
    float src = fmaxf((s + 0.5f) * 0.125f - 0.5f, 0.f);
    int i0 = (int)src;
    int i1 = min(i0 + 1, LW - 1);
    float w1 = src - (float)i0;
    float w0 = 1.f - w1;
    int d = threadIdx.x * 4;
    float4 a = *(const float4*)(lnout + ((size_t)b * LW + i0) * DIM + d);
    float4 c = *(const float4*)(lnout + ((size_t)b * LW + i1) * DIM + d);
    float4 o;
    o.x = a.x * w0 + c.x * w1;
    o.y = a.y * w0 + c.y * w1;
    o.z = a.z * w0 + c.z * w1;
    o.w = a.w * w0 + c.w * w1;
    *(float4*)(out + (size_t)row * DIM + d) = o;
}

// ---------------- launch -----------------------------------------------------
extern "C" void kernel_launch(void* const* d_in, const int* in_sizes, int n_in,
                              void* d_out, int out_size) {
    const int*   text    = (const int*)  d_in[0];
    const float* pe      = (const float*)d_in[1];
    const float* id_w    = (const float*)d_in[2];
    const float* id_b    = (const float*)d_in[3];
    const float* eg      = (const float*)d_in[4];
    const float* ebeta   = (const float*)d_in[5];
    const float* sub_w   = (const float*)d_in[6];
    const float* sub_b   = (const float*)d_in[7];
    const float* sub_th  = (const float*)d_in[8];
    const float* sub_ng  = (const float*)d_in[11];
    const float* sub_nb  = (const float*)d_in[12];
    const float* word_w  = (const float*)d_in[13];
    const float* word_b  = (const float*)d_in[14];
    const float* word_th = (const float*)d_in[15];
    const float* word_ng = (const float*)d_in[18];
    const float* word_nb = (const float*)d_in[19];
    const float* qkv_w   = (const float*)d_in[20];
    const float* qkv_b   = (const float*)d_in[21];
    const float* node_w  = (const float*)d_in[22];
    const float* node_b  = (const float*)d_in[23];
    const float* node_th = (const float*)d_in[24];
    const float* node_tau= (const float*)d_in[25];
    const float* node_vr = (const float*)d_in[26];
    const float* out_ng  = (const float*)d_in[27];
    const float* out_nb  = (const float*)d_in[28];

    float *fused1, *proj, *fused2, *word, *ta, *tb, *tk, *tv, *state, *attn, *lnout;
    cudaGetSymbolAddress((void**)&fused1, g_fused1);
    cudaGetSymbolAddress((void**)&proj,   g_proj);
    cudaGetSymbolAddress((void**)&fused2, g_fused2);
    cudaGetSymbolAddress((void**)&word,   g_word);
    cudaGetSymbolAddress((void**)&ta,     g_ta);
    cudaGetSymbolAddress((void**)&tb,     g_tb);
    cudaGetSymbolAddress((void**)&tk,     g_treek);
    cudaGetSymbolAddress((void**)&tv,     g_treev);
    cudaGetSymbolAddress((void**)&state,  g_state);
    cudaGetSymbolAddress((void**)&attn,   g_attn);
    cudaGetSymbolAddress((void**)&lnout,  g_lnout);

    // 1. char embed + LN + pool2
    embed_pool2_kernel<<<BATCH * LS, 128>>>(text, pe, id_w, id_b, eg, ebeta, fused1);

    // 2. sub: GEMM + fused (spike/residual/LN + mean-pool4) epilogue
    {
        dim3 grid(DIM / BN, (BATCH * LS) / BM);
        sgemm_nt<<<grid, 256>>>(fused1, sub_w, sub_b, proj, BATCH * LS, DIM, DIM);
    }
    fuse_epi_pool4_kernel<<<BATCH * LW, 128>>>(proj, fused1, sub_th, sub_ng, sub_nb, fused2);

    // 3. word: GEMM + epilogue
    {
        dim3 grid(DIM / BN, (BATCH * LW) / BM);
        sgemm_nt<<<grid, 256>>>(fused2, word_w, word_b, proj, BATCH * LW, DIM, DIM);
    }
    fuse_epi_kernel<<<BATCH * LW, 128>>>(proj, fused2, word_th, word_ng, word_nb, word);

    // 4. qkv GEMM (bias folded in); result lives in g_proj
    {
        dim3 grid((3 * DIM) / BN, (BATCH * LW) / BM);
        sgemm_nt<<<grid, 256>>>(word, qkv_w, qkv_b, proj, BATCH * LW, 3 * DIM, DIM);
    }

    // 5. tree: K pass (writes LIF state)
    tree_level_kernel<<<BATCH * NH * 8, 256>>>(proj, 1, 1, 7, 8, 1,
        node_w, node_b, node_th, node_tau, node_vr, ta, state);
    tree_level_kernel<<<BATCH * NH * 4, 256>>>(ta, 0, 0, 3, 4, 1,
        node_w, node_b, node_th, node_tau, node_vr, tb, state);
    tree_level_kernel<<<BATCH * NH * 2, 256>>>(tb, 0, 0, 1, 2, 1,
        node_w, node_b, node_th, node_tau, node_vr, ta, state);
    tree_level_kernel<<<BATCH * NH * 1, 256>>>(ta, 0, 0, 0, 1, 1,
        node_w, node_b, node_th, node_tau, node_vr, tk, state);

    // 6. tree: V pass (reads K-pass state; no state write)
    tree_level_kernel<<<BATCH * NH * 8, 256>>>(proj, 1, 2, 7, 8, 0,
        node_w, node_b, node_th, node_tau, node_vr, ta, state);
    tree_level_kernel<<<BATCH * NH * 4, 256>>>(ta, 0, 0, 3, 4, 0,
        node_w, node_b, node_th, node_tau, node_vr, tb, state);
    tree_level_kernel<<<BATCH * NH * 2, 256>>>(tb, 0, 0, 1, 2, 0,
        node_w, node_b, node_th, node_tau, node_vr, ta, state);
    tree_level_kernel<<<BATCH * NH * 1, 256>>>(ta, 0, 0, 0, 1, 0,
        node_w, node_b, node_th, node_tau, node_vr, tv, state);

    // 7. attention + output LN + interpolation
    attn_kernel<<<BATCH * NH, 256>>>(proj, tk, tv, attn);
    out_ln_kernel<<<BATCH * LW, 128>>>(attn, word, out_ng, out_nb, lnout);
    interp_kernel<<<BATCH * SEQ, 128>>>(lnout, (float*)d_out);
}